// round 4
// baseline (speedup 1.0000x reference)
#include <cuda_runtime.h>
#include <math.h>

#define BATCH        2048
#define IN_DIM       4096
#define OUT_DIM      1024
#define N_EDGES_MAX  16384
#define ROWS_PER_BLK 4
#define THREADS      1024
#define EPT          16      // edges per thread: THREADS*EPT == N_EDGES_MAX

// Packed edges: (src | dst<<12, weight_bits). src<4096 (12b), dst<1024 (10b).
__device__ int2 g_edges[N_EDGES_MAX];

__global__ void prologue_kernel(const int* __restrict__ edge_src,
                                const float* __restrict__ weights,
                                const int* __restrict__ edge_dst,
                                int n_edges) {
    int i = blockIdx.x * blockDim.x + threadIdx.x;
    if (i < n_edges)
        g_edges[i] = make_int2(edge_src[i] | (edge_dst[i] << 12),
                               __float_as_int(weights[i]));
}

// smem: xs_t[IN_DIM] float4 (64 KB, transposed 4-row tile of x)
//       acc[4][OUT_DIM] float (16 KB, scatter accumulators)
extern __shared__ float smem_raw[];

__global__ __launch_bounds__(THREADS, 2)
void sparse_node_main_kernel(const float* __restrict__ x,
                             float* __restrict__ out,
                             int n_edges) {
    float4* xs_t = reinterpret_cast<float4*>(smem_raw);   // [IN_DIM]
    float*  acc  = smem_raw + 4 * IN_DIM;                  // [4][OUT_DIM]

    const int r0 = blockIdx.x * ROWS_PER_BLK;
    const int t  = threadIdx.x;

    // ---- Stage 4 rows of x, transposed: xs_t[s] = {x[r0][s],...,x[r0+3][s]} ----
    {
        const float4* __restrict__ xg = reinterpret_cast<const float4*>(x);
        const int row_q = IN_DIM / 4;
        float4 a0 = xg[(size_t)(r0 + 0) * row_q + t];
        float4 a1 = xg[(size_t)(r0 + 1) * row_q + t];
        float4 a2 = xg[(size_t)(r0 + 2) * row_q + t];
        float4 a3 = xg[(size_t)(r0 + 3) * row_q + t];
        float4 c[4];
        c[0] = make_float4(a0.x, a1.x, a2.x, a3.x);
        c[1] = make_float4(a0.y, a1.y, a2.y, a3.y);
        c[2] = make_float4(a0.z, a1.z, a2.z, a3.z);
        c[3] = make_float4(a0.w, a1.w, a2.w, a3.w);
        #pragma unroll
        for (int i = 0; i < 4; i++) {
            int j = (i + t) & 3;
            xs_t[4 * t + j] = c[j];
        }
    }
    // ---- Zero accumulators ----
    #pragma unroll
    for (int r = 0; r < 4; r++) acc[r * OUT_DIM + t] = 0.0f;
    __syncthreads();

    // ---- Dense edge walk: thread t owns edges [t*EPT, t*EPT+EPT).
    // All lanes active every iteration => exactly EPT warp-LDS.128 per warp.
    // dst-sorted => a chunk spans ~2 nodes; flush local float4 on change. ----
    {
        const int e0 = t * EPT;
        float4 lacc = make_float4(0.f, 0.f, 0.f, 0.f);
        int cur_d = -1;
        #pragma unroll 4
        for (int i = 0; i < EPT; i++) {
            const int e = e0 + i;
            if (e >= n_edges) break;
            const int2 p = __ldg(&g_edges[e]);
            const int s = p.x & 0xFFF;
            const int d = (p.x >> 12) & 0x3FF;
            const float w = __int_as_float(p.y);
            if (d != cur_d) {
                if (cur_d >= 0) {
                    atomicAdd(&acc[0 * OUT_DIM + cur_d], lacc.x);
                    atomicAdd(&acc[1 * OUT_DIM + cur_d], lacc.y);
                    atomicAdd(&acc[2 * OUT_DIM + cur_d], lacc.z);
                    atomicAdd(&acc[3 * OUT_DIM + cur_d], lacc.w);
                }
                lacc = make_float4(0.f, 0.f, 0.f, 0.f);
                cur_d = d;
            }
            const float4 v = xs_t[s];
            lacc.x = fmaf(v.x, w, lacc.x);
            lacc.y = fmaf(v.y, w, lacc.y);
            lacc.z = fmaf(v.z, w, lacc.z);
            lacc.w = fmaf(v.w, w, lacc.w);
        }
        if (cur_d >= 0) {
            atomicAdd(&acc[0 * OUT_DIM + cur_d], lacc.x);
            atomicAdd(&acc[1 * OUT_DIM + cur_d], lacc.y);
            atomicAdd(&acc[2 * OUT_DIM + cur_d], lacc.z);
            atomicAdd(&acc[3 * OUT_DIM + cur_d], lacc.w);
        }
    }
    __syncthreads();

    // ---- Epilogue: tanh -> sigmoid, coalesced stores (node t, 4 rows) ----
    #pragma unroll
    for (int r = 0; r < 4; r++) {
        float h  = tanhf(acc[r * OUT_DIM + t]);
        float sg = 1.0f / (1.0f + __expf(-h));
        out[(size_t)(r0 + r) * OUT_DIM + t] = sg;
    }
}

extern "C" void kernel_launch(void* const* d_in, const int* in_sizes, int n_in,
                              void* d_out, int out_size) {
    const float* x        = (const float*)d_in[0];   // [2048, 4096] f32
    const float* weights  = (const float*)d_in[1];   // [16384] f32
    const int*   edge_src = (const int*)d_in[2];     // [16384] i32
    const int*   edge_dst = (const int*)d_in[3];     // [16384] i32 (sorted)
    float*       out      = (float*)d_out;           // [2048, 1024] f32

    const int n_edges = in_sizes[1];
    const size_t smem = (size_t)(4 * IN_DIM + 4 * OUT_DIM) * sizeof(float); // 80 KB

    static bool attr_set = false;
    if (!attr_set) {
        cudaFuncSetAttribute(sparse_node_main_kernel,
                             cudaFuncAttributeMaxDynamicSharedMemorySize,
                             (int)smem);
        attr_set = true;
    }

    prologue_kernel<<<(n_edges + 127) / 128, 128>>>(edge_src, weights,
                                                    edge_dst, n_edges);

    const int grid = BATCH / ROWS_PER_BLK;  // 512
    sparse_node_main_kernel<<<grid, THREADS, smem>>>(x, out, n_edges);
}

// round 6
// speedup vs baseline: 1.9458x; 1.9458x over previous
#include <cuda_runtime.h>
#include <math.h>

#define BATCH        2048
#define IN_DIM       4096
#define OUT_DIM      1024
#define N_EDGES_MAX  16384

#define BT           256    // batch-tile per gather block
#define NPB          8      // nodes (warps) per gather block

// Scratch (no allocations allowed): transposed x + CSR meta.
__device__ float g_xt[(size_t)IN_DIM * BATCH];   // 32 MB, x_t[s][b]
__device__ int   g_offs[OUT_DIM + 1];
__device__ int2  g_edges[N_EDGES_MAX];           // (src, weight_bits)

// ---------------- Prologue: pack edges + CSR offsets ----------------
__global__ void prologue_kernel(const int* __restrict__ edge_src,
                                const float* __restrict__ weights,
                                const int* __restrict__ edge_dst,
                                int n_edges) {
    int i = blockIdx.x * blockDim.x + threadIdx.x;
    if (i < n_edges)
        g_edges[i] = make_int2(edge_src[i], __float_as_int(weights[i]));
    if (i <= OUT_DIM) {
        int lo = 0, hi = n_edges;
        while (lo < hi) {
            int mid = (lo + hi) >> 1;
            if (edge_dst[mid] < i) lo = mid + 1; else hi = mid;
        }
        g_offs[i] = lo;
    }
}

// ---------------- Transpose: x[B][IN] -> x_t[IN][B] ----------------
__global__ __launch_bounds__(256)
void transpose_kernel(const float* __restrict__ x) {
    __shared__ float tile[32][33];
    const int tx = threadIdx.x, ty = threadIdx.y;
    const int c0 = blockIdx.x * 32;   // IN_DIM tile base
    const int b0 = blockIdx.y * 32;   // BATCH tile base
    #pragma unroll
    for (int i = 0; i < 4; i++)
        tile[ty + i * 8][tx] = x[(size_t)(b0 + ty + i * 8) * IN_DIM + c0 + tx];
    __syncthreads();
    #pragma unroll
    for (int i = 0; i < 4; i++)
        g_xt[(size_t)(c0 + ty + i * 8) * BATCH + b0 + tx] = tile[tx][ty + i * 8];
}

// ---------------- Gather: warp-per-node, coalesced row reads ----------------
__device__ __forceinline__ float4 fma4(float4 v, float w, float4 a) {
    a.x = fmaf(v.x, w, a.x);
    a.y = fmaf(v.y, w, a.y);
    a.z = fmaf(v.z, w, a.z);
    a.w = fmaf(v.w, w, a.w);
    return a;
}
__device__ __forceinline__ float act(float v) {
    float h = tanhf(v);
    return 1.0f / (1.0f + __expf(-h));
}

__global__ __launch_bounds__(NPB * 32)
void gather_kernel(float* __restrict__ out) {
    const int warp = threadIdx.x >> 5;
    const int lane = threadIdx.x & 31;
    const int o    = blockIdx.y * NPB + warp;          // node
    const int bq0  = blockIdx.x * (BT / 4);            // float4 base in batch

    const float4* __restrict__ xt4 = reinterpret_cast<const float4*>(g_xt);
    const int beg = g_offs[o];
    const int end = g_offs[o + 1];

    float4 a0 = make_float4(0.f, 0.f, 0.f, 0.f);
    float4 a1 = make_float4(0.f, 0.f, 0.f, 0.f);

    int e = beg;
    for (; e + 1 < end; e += 2) {
        int2 p0 = g_edges[e];
        int2 p1 = g_edges[e + 1];
        const float4* r0 = xt4 + (size_t)p0.x * (BATCH / 4);
        const float4* r1 = xt4 + (size_t)p1.x * (BATCH / 4);
        float4 v00 = r0[bq0 + lane];
        float4 v01 = r0[bq0 + 32 + lane];
        float4 v10 = r1[bq0 + lane];
        float4 v11 = r1[bq0 + 32 + lane];
        float w0 = __int_as_float(p0.y);
        float w1 = __int_as_float(p1.y);
        a0 = fma4(v00, w0, a0);
        a1 = fma4(v01, w0, a1);
        a0 = fma4(v10, w1, a0);
        a1 = fma4(v11, w1, a1);
    }
    if (e < end) {
        int2 p = g_edges[e];
        const float4* r = xt4 + (size_t)p.x * (BATCH / 4);
        float w = __int_as_float(p.y);
        a0 = fma4(r[bq0 + lane], w, a0);
        a1 = fma4(r[bq0 + 32 + lane], w, a1);
    }

    // Activations
    a0.x = act(a0.x); a0.y = act(a0.y); a0.z = act(a0.z); a0.w = act(a0.w);
    a1.x = act(a1.x); a1.y = act(a1.y); a1.z = act(a1.z); a1.w = act(a1.w);

    // smem transpose: t[batch_in_tile][node_in_block] for coalesced stores
    __shared__ float t[BT][NPB + 1];
    {
        int b = 4 * lane;
        t[b + 0][warp] = a0.x; t[b + 1][warp] = a0.y;
        t[b + 2][warp] = a0.z; t[b + 3][warp] = a0.w;
        b += 128;
        t[b + 0][warp] = a1.x; t[b + 1][warp] = a1.y;
        t[b + 2][warp] = a1.z; t[b + 3][warp] = a1.w;
    }
    __syncthreads();

    // Thread i stores batch row (b0 + i): 8 contiguous floats -> two float4
    {
        const int i  = threadIdx.x;            // 0..255
        const int b  = blockIdx.x * BT + i;
        float4 s0 = make_float4(t[i][0], t[i][1], t[i][2], t[i][3]);
        float4 s1 = make_float4(t[i][4], t[i][5], t[i][6], t[i][7]);
        float4* dst = reinterpret_cast<float4*>(out + (size_t)b * OUT_DIM
                                                + blockIdx.y * NPB);
        dst[0] = s0;
        dst[1] = s1;
    }
}

extern "C" void kernel_launch(void* const* d_in, const int* in_sizes, int n_in,
                              void* d_out, int out_size) {
    const float* x        = (const float*)d_in[0];   // [2048, 4096] f32
    const float* weights  = (const float*)d_in[1];   // [16384] f32
    const int*   edge_src = (const int*)d_in[2];     // [16384] i32
    const int*   edge_dst = (const int*)d_in[3];     // [16384] i32 (sorted)
    float*       out      = (float*)d_out;           // [2048, 1024] f32

    const int n_edges = in_sizes[1];

    // 1) CSR meta
    int pro = (n_edges > OUT_DIM + 1 ? n_edges : OUT_DIM + 1);
    prologue_kernel<<<(pro + 127) / 128, 128>>>(edge_src, weights,
                                                edge_dst, n_edges);

    // 2) Transpose x -> x_t (coalesced both sides)
    transpose_kernel<<<dim3(IN_DIM / 32, BATCH / 32), dim3(32, 8)>>>(x);

    // 3) Gather: warp-per-node over batch tiles, all reads coalesced
    gather_kernel<<<dim3(BATCH / BT, OUT_DIM / NPB), NPB * 32>>>(out);
}

// round 7
// speedup vs baseline: 2.2449x; 1.1537x over previous
#include <cuda_runtime.h>
#include <math.h>

#define BATCH        2048
#define IN_DIM       4096
#define OUT_DIM      1024
#define N_EDGES_MAX  16384

#define BT           256    // batch-tile per gather block
#define NPB          8      // nodes (warps) per gather block

// Scratch (no allocations allowed): transposed x + CSR meta.
__device__ float g_xt[(size_t)IN_DIM * BATCH];   // 32 MB, x_t[s][b]
__device__ int   g_offs[OUT_DIM + 1];
__device__ int2  g_edges[N_EDGES_MAX];           // (src, weight_bits)

// ---------------- Prologue: pack edges + scatter-built CSR offsets ----------
// offs[o] = first edge index i with dst[i] >= o. dst is sorted ascending.
// Thread i owns the gap (dst[i-1], dst[i]] -> all independent loads, no chain.
__global__ void prologue_kernel(const int* __restrict__ edge_src,
                                const float* __restrict__ weights,
                                const int* __restrict__ edge_dst,
                                int n_edges) {
    int i = blockIdx.x * blockDim.x + threadIdx.x;
    if (i >= n_edges) return;

    g_edges[i] = make_int2(edge_src[i], __float_as_int(weights[i]));

    const int d  = edge_dst[i];
    const int dp = (i == 0) ? -1 : edge_dst[i - 1];
    for (int o = dp + 1; o <= d; o++) g_offs[o] = i;
    if (i == n_edges - 1)
        for (int o = d + 1; o <= OUT_DIM; o++) g_offs[o] = n_edges;
}

// ---------------- Transpose: x[B][IN] -> x_t[IN][B] ----------------
__global__ __launch_bounds__(256)
void transpose_kernel(const float* __restrict__ x) {
    __shared__ float tile[32][33];
    const int tx = threadIdx.x, ty = threadIdx.y;
    const int c0 = blockIdx.x * 32;   // IN_DIM tile base
    const int b0 = blockIdx.y * 32;   // BATCH tile base
    #pragma unroll
    for (int i = 0; i < 4; i++)
        tile[ty + i * 8][tx] = x[(size_t)(b0 + ty + i * 8) * IN_DIM + c0 + tx];
    __syncthreads();
    #pragma unroll
    for (int i = 0; i < 4; i++)
        g_xt[(size_t)(c0 + ty + i * 8) * BATCH + b0 + tx] = tile[tx][ty + i * 8];
}

// ---------------- Gather: warp-per-node, coalesced row reads ----------------
__device__ __forceinline__ float4 fma4(float4 v, float w, float4 a) {
    a.x = fmaf(v.x, w, a.x);
    a.y = fmaf(v.y, w, a.y);
    a.z = fmaf(v.z, w, a.z);
    a.w = fmaf(v.w, w, a.w);
    return a;
}
__device__ __forceinline__ float act(float v) {
    float h = tanhf(v);
    return 1.0f / (1.0f + __expf(-h));
}

__global__ __launch_bounds__(NPB * 32)
void gather_kernel(float* __restrict__ out) {
    const int warp = threadIdx.x >> 5;
    const int lane = threadIdx.x & 31;
    const int o    = blockIdx.y * NPB + warp;          // node (warp-uniform)
    const int bq0  = blockIdx.x * (BT / 4);            // float4 base in batch

    const float4* __restrict__ xt4 = reinterpret_cast<const float4*>(g_xt);
    const int beg = g_offs[o];
    const int end = g_offs[o + 1];

    float4 a0 = make_float4(0.f, 0.f, 0.f, 0.f);
    float4 a1 = make_float4(0.f, 0.f, 0.f, 0.f);

    int e = beg;
    // Unrolled x4: 8 outstanding LDG.128 per warp to hide L2 latency.
    for (; e + 3 < end; e += 4) {
        int2 p0 = g_edges[e + 0];
        int2 p1 = g_edges[e + 1];
        int2 p2 = g_edges[e + 2];
        int2 p3 = g_edges[e + 3];
        const float4* r0 = xt4 + (size_t)p0.x * (BATCH / 4);
        const float4* r1 = xt4 + (size_t)p1.x * (BATCH / 4);
        const float4* r2 = xt4 + (size_t)p2.x * (BATCH / 4);
        const float4* r3 = xt4 + (size_t)p3.x * (BATCH / 4);
        float4 v00 = r0[bq0 + lane];      float4 v01 = r0[bq0 + 32 + lane];
        float4 v10 = r1[bq0 + lane];      float4 v11 = r1[bq0 + 32 + lane];
        float4 v20 = r2[bq0 + lane];      float4 v21 = r2[bq0 + 32 + lane];
        float4 v30 = r3[bq0 + lane];      float4 v31 = r3[bq0 + 32 + lane];
        float w0 = __int_as_float(p0.y);  float w1 = __int_as_float(p1.y);
        float w2 = __int_as_float(p2.y);  float w3 = __int_as_float(p3.y);
        a0 = fma4(v00, w0, a0);  a1 = fma4(v01, w0, a1);
        a0 = fma4(v10, w1, a0);  a1 = fma4(v11, w1, a1);
        a0 = fma4(v20, w2, a0);  a1 = fma4(v21, w2, a1);
        a0 = fma4(v30, w3, a0);  a1 = fma4(v31, w3, a1);
    }
    for (; e < end; e++) {
        int2 p = g_edges[e];
        const float4* r = xt4 + (size_t)p.x * (BATCH / 4);
        float w = __int_as_float(p.y);
        a0 = fma4(r[bq0 + lane], w, a0);
        a1 = fma4(r[bq0 + 32 + lane], w, a1);
    }

    // Activations
    a0.x = act(a0.x); a0.y = act(a0.y); a0.z = act(a0.z); a0.w = act(a0.w);
    a1.x = act(a1.x); a1.y = act(a1.y); a1.z = act(a1.z); a1.w = act(a1.w);

    // smem transpose: t[batch_in_tile][node_in_block] for coalesced stores
    __shared__ float t[BT][NPB + 1];
    {
        int b = 4 * lane;
        t[b + 0][warp] = a0.x; t[b + 1][warp] = a0.y;
        t[b + 2][warp] = a0.z; t[b + 3][warp] = a0.w;
        b += 128;
        t[b + 0][warp] = a1.x; t[b + 1][warp] = a1.y;
        t[b + 2][warp] = a1.z; t[b + 3][warp] = a1.w;
    }
    __syncthreads();

    // Thread i stores batch row (b0 + i): 8 contiguous floats -> two float4
    {
        const int i  = threadIdx.x;            // 0..255
        const int b  = blockIdx.x * BT + i;
        float4 s0 = make_float4(t[i][0], t[i][1], t[i][2], t[i][3]);
        float4 s1 = make_float4(t[i][4], t[i][5], t[i][6], t[i][7]);
        float4* dst = reinterpret_cast<float4*>(out + (size_t)b * OUT_DIM
                                                + blockIdx.y * NPB);
        dst[0] = s0;
        dst[1] = s1;
    }
}

extern "C" void kernel_launch(void* const* d_in, const int* in_sizes, int n_in,
                              void* d_out, int out_size) {
    const float* x        = (const float*)d_in[0];   // [2048, 4096] f32
    const float* weights  = (const float*)d_in[1];   // [16384] f32
    const int*   edge_src = (const int*)d_in[2];     // [16384] i32
    const int*   edge_dst = (const int*)d_in[3];     // [16384] i32 (sorted)
    float*       out      = (float*)d_out;           // [2048, 1024] f32

    const int n_edges = in_sizes[1];

    // 1) CSR meta (scatter-built, no dependent-load chains)
    prologue_kernel<<<(n_edges + 255) / 256, 256>>>(edge_src, weights,
                                                    edge_dst, n_edges);

    // 2) Transpose x -> x_t (coalesced both sides)
    transpose_kernel<<<dim3(IN_DIM / 32, BATCH / 32), dim3(32, 8)>>>(x);

    // 3) Gather: warp-per-node over batch tiles, all reads coalesced
    gather_kernel<<<dim3(BATCH / BT, OUT_DIM / NPB), NPB * 32>>>(out);
}

// round 8
// speedup vs baseline: 2.4024x; 1.0702x over previous
#include <cuda_runtime.h>
#include <math.h>

#define BATCH        2048
#define IN_DIM       4096
#define OUT_DIM      1024
#define N_EDGES_MAX  16384

#define BT           256    // batch-tile per gather block
#define NPB          8      // nodes (warps) per gather block

// Scratch (no allocations allowed): transposed x + CSR meta.
__device__ float g_xt[(size_t)IN_DIM * BATCH];   // 32 MB, x_t[s][b]
__device__ int   g_offs[OUT_DIM + 1];
__device__ int2  g_edges[N_EDGES_MAX];           // (src, weight_bits)

// ---------------- Fused transpose + prologue ----------------
// All blocks: transpose a 32x32 tile of x into g_xt.
// First 64 blocks of row y==0 additionally pack edges and scatter-build the
// CSR offsets (sorted edge_dst: thread i owns destination gap (d[i-1], d[i]]).
// The prologue's independent loads hide under the transpose's DRAM traffic.
__global__ __launch_bounds__(256)
void transpose_prologue_kernel(const float* __restrict__ x,
                               const int* __restrict__ edge_src,
                               const float* __restrict__ weights,
                               const int* __restrict__ edge_dst,
                               int n_edges) {
    const int tx = threadIdx.x, ty = threadIdx.y;

    // ---- Embedded prologue (64 blocks x 256 threads = 16384 lanes) ----
    if (blockIdx.y == 0 && blockIdx.x < 64) {
        const int i = blockIdx.x * 256 + ty * 32 + tx;
        if (i < n_edges) {
            g_edges[i] = make_int2(edge_src[i], __float_as_int(weights[i]));
            const int d  = edge_dst[i];
            const int dp = (i == 0) ? -1 : edge_dst[i - 1];
            for (int o = dp + 1; o <= d; o++) g_offs[o] = i;
            if (i == n_edges - 1)
                for (int o = d + 1; o <= OUT_DIM; o++) g_offs[o] = n_edges;
        }
    }

    // ---- Transpose tile ----
    __shared__ float tile[32][33];
    const int c0 = blockIdx.x * 32;   // IN_DIM tile base
    const int b0 = blockIdx.y * 32;   // BATCH tile base
    #pragma unroll
    for (int i = 0; i < 4; i++)
        tile[ty + i * 8][tx] = x[(size_t)(b0 + ty + i * 8) * IN_DIM + c0 + tx];
    __syncthreads();
    #pragma unroll
    for (int i = 0; i < 4; i++)
        g_xt[(size_t)(c0 + ty + i * 8) * BATCH + b0 + tx] = tile[tx][ty + i * 8];
}

// ---------------- Gather: warp-per-node, coalesced row reads ----------------
__device__ __forceinline__ float4 fma4(float4 v, float w, float4 a) {
    a.x = fmaf(v.x, w, a.x);
    a.y = fmaf(v.y, w, a.y);
    a.z = fmaf(v.z, w, a.z);
    a.w = fmaf(v.w, w, a.w);
    return a;
}
__device__ __forceinline__ float act(float v) {
    float h = tanhf(v);
    return 1.0f / (1.0f + __expf(-h));
}

__global__ __launch_bounds__(NPB * 32)
void gather_kernel(float* __restrict__ out) {
    const int warp = threadIdx.x >> 5;
    const int lane = threadIdx.x & 31;
    const int o    = blockIdx.y * NPB + warp;          // node (warp-uniform)
    const int bq0  = blockIdx.x * (BT / 4);            // float4 base in batch

    const float4* __restrict__ xt4 = reinterpret_cast<const float4*>(g_xt);
    const int beg = g_offs[o];
    const int end = g_offs[o + 1];

    float4 a0 = make_float4(0.f, 0.f, 0.f, 0.f);
    float4 a1 = make_float4(0.f, 0.f, 0.f, 0.f);

    int e = beg;
    // Unrolled x4: 8 outstanding LDG.128 per warp to hide L2 latency.
    for (; e + 3 < end; e += 4) {
        int2 p0 = __ldg(&g_edges[e + 0]);
        int2 p1 = __ldg(&g_edges[e + 1]);
        int2 p2 = __ldg(&g_edges[e + 2]);
        int2 p3 = __ldg(&g_edges[e + 3]);
        const float4* r0 = xt4 + (size_t)p0.x * (BATCH / 4);
        const float4* r1 = xt4 + (size_t)p1.x * (BATCH / 4);
        const float4* r2 = xt4 + (size_t)p2.x * (BATCH / 4);
        const float4* r3 = xt4 + (size_t)p3.x * (BATCH / 4);
        float4 v00 = r0[bq0 + lane];      float4 v01 = r0[bq0 + 32 + lane];
        float4 v10 = r1[bq0 + lane];      float4 v11 = r1[bq0 + 32 + lane];
        float4 v20 = r2[bq0 + lane];      float4 v21 = r2[bq0 + 32 + lane];
        float4 v30 = r3[bq0 + lane];      float4 v31 = r3[bq0 + 32 + lane];
        float w0 = __int_as_float(p0.y);  float w1 = __int_as_float(p1.y);
        float w2 = __int_as_float(p2.y);  float w3 = __int_as_float(p3.y);
        a0 = fma4(v00, w0, a0);  a1 = fma4(v01, w0, a1);
        a0 = fma4(v10, w1, a0);  a1 = fma4(v11, w1, a1);
        a0 = fma4(v20, w2, a0);  a1 = fma4(v21, w2, a1);
        a0 = fma4(v30, w3, a0);  a1 = fma4(v31, w3, a1);
    }
    for (; e < end; e++) {
        int2 p = __ldg(&g_edges[e]);
        const float4* r = xt4 + (size_t)p.x * (BATCH / 4);
        float w = __int_as_float(p.y);
        a0 = fma4(r[bq0 + lane], w, a0);
        a1 = fma4(r[bq0 + 32 + lane], w, a1);
    }

    // Activations
    a0.x = act(a0.x); a0.y = act(a0.y); a0.z = act(a0.z); a0.w = act(a0.w);
    a1.x = act(a1.x); a1.y = act(a1.y); a1.z = act(a1.z); a1.w = act(a1.w);

    // smem transpose: t[batch_in_tile][node_in_block] for coalesced stores
    __shared__ float t[BT][NPB + 1];
    {
        int b = 4 * lane;
        t[b + 0][warp] = a0.x; t[b + 1][warp] = a0.y;
        t[b + 2][warp] = a0.z; t[b + 3][warp] = a0.w;
        b += 128;
        t[b + 0][warp] = a1.x; t[b + 1][warp] = a1.y;
        t[b + 2][warp] = a1.z; t[b + 3][warp] = a1.w;
    }
    __syncthreads();

    // Thread i stores batch row (b0 + i): 8 contiguous floats -> two float4
    {
        const int i  = threadIdx.x;            // 0..255
        const int b  = blockIdx.x * BT + i;
        float4 s0 = make_float4(t[i][0], t[i][1], t[i][2], t[i][3]);
        float4 s1 = make_float4(t[i][4], t[i][5], t[i][6], t[i][7]);
        float4* dst = reinterpret_cast<float4*>(out + (size_t)b * OUT_DIM
                                                + blockIdx.y * NPB);
        dst[0] = s0;
        dst[1] = s1;
    }
}

extern "C" void kernel_launch(void* const* d_in, const int* in_sizes, int n_in,
                              void* d_out, int out_size) {
    const float* x        = (const float*)d_in[0];   // [2048, 4096] f32
    const float* weights  = (const float*)d_in[1];   // [16384] f32
    const int*   edge_src = (const int*)d_in[2];     // [16384] i32
    const int*   edge_dst = (const int*)d_in[3];     // [16384] i32 (sorted)
    float*       out      = (float*)d_out;           // [2048, 1024] f32

    const int n_edges = in_sizes[1];

    // 1) Fused transpose + CSR-meta build (prologue hides under DRAM traffic)
    transpose_prologue_kernel<<<dim3(IN_DIM / 32, BATCH / 32), dim3(32, 8)>>>(
        x, edge_src, weights, edge_dst, n_edges);

    // 2) Gather: warp-per-node over batch tiles, all reads coalesced
    gather_kernel<<<dim3(BATCH / BT, OUT_DIM / NPB), NPB * 32>>>(out);
}

// round 9
// speedup vs baseline: 2.5807x; 1.0742x over previous
#include <cuda_runtime.h>
#include <math.h>

#define BATCH        2048
#define IN_DIM       4096
#define OUT_DIM      1024
#define N_EDGES_MAX  16384

#define BT           256    // batch-tile per gather block
#define NPB          8      // nodes (warps) per gather block

// Scratch (no allocations allowed): transposed x + CSR meta.
__device__ float g_xt[(size_t)IN_DIM * BATCH];   // 32 MB, x_t[s][b] (L2-resident)
__device__ int   g_offs[OUT_DIM + 1];
__device__ int2  g_edges[N_EDGES_MAX];           // (src, weight_bits)

// ---------------- Fused transpose + prologue ----------------
__global__ __launch_bounds__(256)
void transpose_prologue_kernel(const float* __restrict__ x,
                               const int* __restrict__ edge_src,
                               const float* __restrict__ weights,
                               const int* __restrict__ edge_dst,
                               int n_edges) {
    const int tx = threadIdx.x, ty = threadIdx.y;

    // ---- Embedded prologue (64 blocks x 256 threads = 16384 lanes) ----
    if (blockIdx.y == 0 && blockIdx.x < 64) {
        const int i = blockIdx.x * 256 + ty * 32 + tx;
        if (i < n_edges) {
            g_edges[i] = make_int2(edge_src[i], __float_as_int(weights[i]));
            const int d  = edge_dst[i];
            const int dp = (i == 0) ? -1 : edge_dst[i - 1];
            for (int o = dp + 1; o <= d; o++) g_offs[o] = i;
            if (i == n_edges - 1)
                for (int o = d + 1; o <= OUT_DIM; o++) g_offs[o] = n_edges;
        }
    }

    // ---- Transpose tile ----
    __shared__ float tile[32][33];
    const int c0 = blockIdx.x * 32;   // IN_DIM tile base
    const int b0 = blockIdx.y * 32;   // BATCH tile base
    #pragma unroll
    for (int i = 0; i < 4; i++)
        tile[ty + i * 8][tx] = x[(size_t)(b0 + ty + i * 8) * IN_DIM + c0 + tx];
    __syncthreads();
    #pragma unroll
    for (int i = 0; i < 4; i++)
        g_xt[(size_t)(c0 + ty + i * 8) * BATCH + b0 + tx] = tile[tx][ty + i * 8];
}

// ---------------- Gather: warp-per-node, shfl-broadcast edge meta ----------
__device__ __forceinline__ float4 fma4(float4 v, float w, float4 a) {
    a.x = fmaf(v.x, w, a.x);
    a.y = fmaf(v.y, w, a.y);
    a.z = fmaf(v.z, w, a.z);
    a.w = fmaf(v.w, w, a.w);
    return a;
}
__device__ __forceinline__ float act(float v) {
    float h = tanhf(v);
    return 1.0f / (1.0f + __expf(-h));
}

__global__ __launch_bounds__(NPB * 32)
void gather_kernel(float* __restrict__ out) {
    const int warp = threadIdx.x >> 5;
    const int lane = threadIdx.x & 31;
    const int o    = blockIdx.y * NPB + warp;          // node (warp-uniform)
    const int bq0  = blockIdx.x * (BT / 4);            // float4 base in batch

    const float4* __restrict__ xt4 = reinterpret_cast<const float4*>(g_xt);
    const int beg = g_offs[o];
    const int cnt = g_offs[o + 1] - beg;

    float4 a0 = make_float4(0.f, 0.f, 0.f, 0.f);
    float4 a1 = make_float4(0.f, 0.f, 0.f, 0.f);

    // Process edges in warp-sized chunks: ONE cooperative LDG.64 fetches up to
    // 32 edges, then shfl (register-only) broadcasts each (src, w). All x_t
    // addresses become register-derived -> LDG.128s stream with no mem->addr
    // dependency, fully software-pipelineable.
    for (int base = 0; base < cnt; base += 32) {
        const int rem = min(32, cnt - base);
        int2 ep = make_int2(0, 0);
        if (lane < rem) ep = __ldg(&g_edges[beg + base + lane]);

        int i = 0;
        for (; i + 3 < rem; i += 4) {
            int   s0 = __shfl_sync(0xFFFFFFFFu, ep.x, i + 0);
            float w0 = __int_as_float(__shfl_sync(0xFFFFFFFFu, ep.y, i + 0));
            int   s1 = __shfl_sync(0xFFFFFFFFu, ep.x, i + 1);
            float w1 = __int_as_float(__shfl_sync(0xFFFFFFFFu, ep.y, i + 1));
            int   s2 = __shfl_sync(0xFFFFFFFFu, ep.x, i + 2);
            float w2 = __int_as_float(__shfl_sync(0xFFFFFFFFu, ep.y, i + 2));
            int   s3 = __shfl_sync(0xFFFFFFFFu, ep.x, i + 3);
            float w3 = __int_as_float(__shfl_sync(0xFFFFFFFFu, ep.y, i + 3));
            const float4* r0 = xt4 + (size_t)s0 * (BATCH / 4);
            const float4* r1 = xt4 + (size_t)s1 * (BATCH / 4);
            const float4* r2 = xt4 + (size_t)s2 * (BATCH / 4);
            const float4* r3 = xt4 + (size_t)s3 * (BATCH / 4);
            float4 v00 = r0[bq0 + lane];      float4 v01 = r0[bq0 + 32 + lane];
            float4 v10 = r1[bq0 + lane];      float4 v11 = r1[bq0 + 32 + lane];
            float4 v20 = r2[bq0 + lane];      float4 v21 = r2[bq0 + 32 + lane];
            float4 v30 = r3[bq0 + lane];      float4 v31 = r3[bq0 + 32 + lane];
            a0 = fma4(v00, w0, a0);  a1 = fma4(v01, w0, a1);
            a0 = fma4(v10, w1, a0);  a1 = fma4(v11, w1, a1);
            a0 = fma4(v20, w2, a0);  a1 = fma4(v21, w2, a1);
            a0 = fma4(v30, w3, a0);  a1 = fma4(v31, w3, a1);
        }
        for (; i < rem; i++) {
            int   s = __shfl_sync(0xFFFFFFFFu, ep.x, i);
            float w = __int_as_float(__shfl_sync(0xFFFFFFFFu, ep.y, i));
            const float4* r = xt4 + (size_t)s * (BATCH / 4);
            a0 = fma4(r[bq0 + lane], w, a0);
            a1 = fma4(r[bq0 + 32 + lane], w, a1);
        }
    }

    // Activations
    a0.x = act(a0.x); a0.y = act(a0.y); a0.z = act(a0.z); a0.w = act(a0.w);
    a1.x = act(a1.x); a1.y = act(a1.y); a1.z = act(a1.z); a1.w = act(a1.w);

    // smem transpose: t[batch_in_tile][node_in_block] for coalesced stores
    __shared__ float t[BT][NPB + 1];
    {
        int b = 4 * lane;
        t[b + 0][warp] = a0.x; t[b + 1][warp] = a0.y;
        t[b + 2][warp] = a0.z; t[b + 3][warp] = a0.w;
        b += 128;
        t[b + 0][warp] = a1.x; t[b + 1][warp] = a1.y;
        t[b + 2][warp] = a1.z; t[b + 3][warp] = a1.w;
    }
    __syncthreads();

    // Thread i stores batch row (b0 + i): 8 contiguous floats -> two float4
    {
        const int i  = threadIdx.x;            // 0..255
        const int b  = blockIdx.x * BT + i;
        float4 s0 = make_float4(t[i][0], t[i][1], t[i][2], t[i][3]);
        float4 s1 = make_float4(t[i][4], t[i][5], t[i][6], t[i][7]);
        float4* dst = reinterpret_cast<float4*>(out + (size_t)b * OUT_DIM
                                                + blockIdx.y * NPB);
        dst[0] = s0;
        dst[1] = s1;
    }
}

extern "C" void kernel_launch(void* const* d_in, const int* in_sizes, int n_in,
                              void* d_out, int out_size) {
    const float* x        = (const float*)d_in[0];   // [2048, 4096] f32
    const float* weights  = (const float*)d_in[1];   // [16384] f32
    const int*   edge_src = (const int*)d_in[2];     // [16384] i32
    const int*   edge_dst = (const int*)d_in[3];     // [16384] i32 (sorted)
    float*       out      = (float*)d_out;           // [2048, 1024] f32

    const int n_edges = in_sizes[1];

    // 1) Fused transpose + CSR-meta build (prologue hides under DRAM traffic)
    transpose_prologue_kernel<<<dim3(IN_DIM / 32, BATCH / 32), dim3(32, 8)>>>(
        x, edge_src, weights, edge_dst, n_edges);

    // 2) Gather: warp-per-node over batch tiles, all reads coalesced
    gather_kernel<<<dim3(BATCH / BT, OUT_DIM / NPB), NPB * 32>>>(out);
}